// round 4
// baseline (speedup 1.0000x reference)
#include <cuda_runtime.h>

#define NBLOCKS 888     // 6 CTAs/SM x 148 SMs -> exactly one wave
#define NTHREADS 256

// Per-block partials (overwritten every call — no zeroing needed).
__device__ float        g_part_iou[NBLOCKS];
__device__ float        g_part_mse[NBLOCKS];
__device__ unsigned int g_part_ninc[NBLOCKS];
// Completion counter; the last block resets it to 0 -> replay-safe.
__device__ unsigned int g_done_count = 0;

__device__ __forceinline__ float4 ldcs4(const float4* p) {
    return __ldcs(p);   // streaming (evict-first): no reuse, don't pollute L2
}

__device__ __forceinline__ void process_box(const float4 p, const float4 g,
                                            float& iou_acc, float& mse_acc,
                                            unsigned int& ninc)
{
    // gt corners (cx, cy, w, h -> xyxy)
    float xminT = g.x - g.z * 0.5f;
    float xmaxT = g.x + g.z * 0.5f;
    float yminT = g.y - g.w * 0.5f;
    float ymaxT = g.y + g.w * 0.5f;
    // pred corners clipped to [0,1]
    float xminP = fmaxf(p.x - p.z * 0.5f, 0.0f);
    float xmaxP = fminf(p.x + p.z * 0.5f, 1.0f);
    float yminP = fmaxf(p.y - p.w * 0.5f, 0.0f);
    float ymaxP = fminf(p.y + p.w * 0.5f, 1.0f);
    // overlap box
    float o0 = fmaxf(xminT, xminP);
    float o1 = fmaxf(yminT, yminP);
    float o2 = fminf(xmaxT, xmaxP);
    float o3 = fminf(ymaxT, ymaxP);

    bool incorrect = (o2 < o0) || (o3 < o1);
    if (incorrect) {
        float dx = p.x - g.x;
        float dy = p.y - g.y;
        float dz = p.z - g.z;
        float dw = p.w - g.w;
        mse_acc += dx * dx + dy * dy + dz * dz + dw * dw;
        ninc++;
    } else {
        float area_p = p.z * p.w;
        float area_g = g.z * g.w;
        float inter  = (o2 - o0) * (o3 - o1);
        iou_acc += inter / (area_p + area_g - inter + 1e-7f);
    }
}

__global__ __launch_bounds__(NTHREADS, 6) void iou_fused_kernel(
    const float4* __restrict__ pr, const float4* __restrict__ gt,
    float* __restrict__ out, int n)
{
    float iou_acc = 0.0f, mse_acc = 0.0f;
    unsigned int ninc = 0u;

    const int tid    = blockIdx.x * NTHREADS + threadIdx.x;
    const int stride = NBLOCKS * NTHREADS;

    int i = tid;
    // Unroll x4: 8 independent 128-bit loads in flight per trip.
    for (; i + 3 * stride < n; i += 4 * stride) {
        float4 p0 = ldcs4(&pr[i]);
        float4 g0 = ldcs4(&gt[i]);
        float4 p1 = ldcs4(&pr[i + stride]);
        float4 g1 = ldcs4(&gt[i + stride]);
        float4 p2 = ldcs4(&pr[i + 2 * stride]);
        float4 g2 = ldcs4(&gt[i + 2 * stride]);
        float4 p3 = ldcs4(&pr[i + 3 * stride]);
        float4 g3 = ldcs4(&gt[i + 3 * stride]);
        process_box(p0, g0, iou_acc, mse_acc, ninc);
        process_box(p1, g1, iou_acc, mse_acc, ninc);
        process_box(p2, g2, iou_acc, mse_acc, ninc);
        process_box(p3, g3, iou_acc, mse_acc, ninc);
    }
    for (; i < n; i += stride) {
        process_box(ldcs4(&pr[i]), ldcs4(&gt[i]), iou_acc, mse_acc, ninc);
    }

    // ncorr is derived: boxes this thread processed minus its ninc.
    // nproc = ceil((n - tid) / stride) for tid < n else 0.
    unsigned int nproc = (tid < n) ? (unsigned int)((n - tid + stride - 1) / stride) : 0u;
    unsigned int ncorr = nproc - ninc;

    // Intra-warp reduce
    #pragma unroll
    for (int off = 16; off > 0; off >>= 1) {
        iou_acc += __shfl_down_sync(0xFFFFFFFFu, iou_acc, off);
        mse_acc += __shfl_down_sync(0xFFFFFFFFu, mse_acc, off);
        ninc    += __shfl_down_sync(0xFFFFFFFFu, ninc, off);
        ncorr   += __shfl_down_sync(0xFFFFFFFFu, ncorr, off);
    }

    // Inter-warp reduce via smem
    __shared__ float s_iou[NTHREADS / 32];
    __shared__ float s_mse[NTHREADS / 32];
    __shared__ unsigned int s_ninc[NTHREADS / 32];
    __shared__ unsigned int s_ncorr[NTHREADS / 32];
    const int lane = threadIdx.x & 31;
    const int warp = threadIdx.x >> 5;
    if (lane == 0) {
        s_iou[warp]   = iou_acc;
        s_mse[warp]   = mse_acc;
        s_ninc[warp]  = ninc;
        s_ncorr[warp] = ncorr;
    }
    __syncthreads();
    if (warp == 0) {
        const int nw = NTHREADS / 32;
        float iou = (lane < nw) ? s_iou[lane] : 0.0f;
        float mse = (lane < nw) ? s_mse[lane] : 0.0f;
        unsigned int ni = (lane < nw) ? s_ninc[lane]  : 0u;
        unsigned int nc = (lane < nw) ? s_ncorr[lane] : 0u;
        #pragma unroll
        for (int off = 4; off > 0; off >>= 1) {
            iou += __shfl_down_sync(0xFFFFFFFFu, iou, off);
            mse += __shfl_down_sync(0xFFFFFFFFu, mse, off);
            ni  += __shfl_down_sync(0xFFFFFFFFu, ni, off);
            nc  += __shfl_down_sync(0xFFFFFFFFu, nc, off);
        }
        if (lane == 0) {
            g_part_iou[blockIdx.x]  = iou;
            g_part_mse[blockIdx.x]  = mse;
            g_part_ninc[blockIdx.x] = ni;
            // ncorr partial not stored: total ncorr = n - total ninc
        }
    }

    // Last-block-done finalization
    __shared__ bool is_last;
    if (threadIdx.x == 0) {
        __threadfence();
        unsigned int prev = atomicAdd(&g_done_count, 1u);
        is_last = (prev == (unsigned int)(gridDim.x - 1));
    }
    __syncthreads();
    if (!is_last) return;

    float iou = 0.0f, mse = 0.0f;
    unsigned long long ni = 0ull;
    for (int j = threadIdx.x; j < NBLOCKS; j += NTHREADS) {
        iou += g_part_iou[j];
        mse += g_part_mse[j];
        ni  += g_part_ninc[j];
    }
    #pragma unroll
    for (int off = 16; off > 0; off >>= 1) {
        iou += __shfl_down_sync(0xFFFFFFFFu, iou, off);
        mse += __shfl_down_sync(0xFFFFFFFFu, mse, off);
        ni  += __shfl_down_sync(0xFFFFFFFFu, ni, off);
    }
    __shared__ float f_iou[NTHREADS / 32];
    __shared__ float f_mse[NTHREADS / 32];
    __shared__ unsigned long long f_ninc[NTHREADS / 32];
    if (lane == 0) {
        f_iou[warp] = iou; f_mse[warp] = mse; f_ninc[warp] = ni;
    }
    __syncthreads();
    if (threadIdx.x == 0) {
        const int nw = NTHREADS / 32;
        double diou = 0.0, dmse = 0.0;
        unsigned long long tninc = 0ull;
        for (int w = 0; w < nw; w++) {
            diou += (double)f_iou[w];
            dmse += (double)f_mse[w];
            tninc += f_ninc[w];
        }
        unsigned long long tncorr = (unsigned long long)n - tninc;
        double mse_denom  = (double)(tninc * 4ull > 0ull ? tninc * 4ull : 1ull);
        double corr_denom = (double)(tncorr > 0ull ? tncorr : 1ull);
        float mse_mean = (float)(dmse / mse_denom);
        float iou_mean = (float)(diou / corr_denom);
        float res_full = iou_mean + (tninc > 0ull ? -mse_mean : 0.0f);
        out[0] = (tncorr > 0ull) ? res_full : -mse_mean;
        g_done_count = 0u;  // reset for next graph replay
    }
}

extern "C" void kernel_launch(void* const* d_in, const int* in_sizes, int n_in,
                              void* d_out, int out_size) {
    const float4* pr = (const float4*)d_in[0];
    const float4* gt = (const float4*)d_in[1];
    float* out = (float*)d_out;
    int n = in_sizes[0] / 4;  // floats -> boxes

    iou_fused_kernel<<<NBLOCKS, NTHREADS>>>(pr, gt, out, n);
}

// round 5
// speedup vs baseline: 1.1626x; 1.1626x over previous
#include <cuda_runtime.h>

#define NBLOCKS 740     // 5 CTAs/SM x 148 SMs -> exactly one wave
#define NTHREADS 256

// Per-block partials (overwritten every call — no zeroing needed).
__device__ float        g_part_iou[NBLOCKS];
__device__ float        g_part_mse[NBLOCKS];
__device__ unsigned int g_part_ninc[NBLOCKS];
// Completion counter; the last block resets it to 0 -> replay-safe.
__device__ unsigned int g_done_count = 0;

__device__ __forceinline__ float4 ldcs4(const float4* p) {
    return __ldcs(p);   // streaming (evict-first): no reuse, don't pollute L2
}

__device__ __forceinline__ void process_box(const float4 p, const float4 g,
                                            float& iou_acc, float& mse_acc,
                                            unsigned int& ninc)
{
    // gt corners (cx, cy, w, h -> xyxy)
    float xminT = g.x - g.z * 0.5f;
    float xmaxT = g.x + g.z * 0.5f;
    float yminT = g.y - g.w * 0.5f;
    float ymaxT = g.y + g.w * 0.5f;
    // pred corners clipped to [0,1]
    float xminP = fmaxf(p.x - p.z * 0.5f, 0.0f);
    float xmaxP = fminf(p.x + p.z * 0.5f, 1.0f);
    float yminP = fmaxf(p.y - p.w * 0.5f, 0.0f);
    float ymaxP = fminf(p.y + p.w * 0.5f, 1.0f);
    // overlap box
    float o0 = fmaxf(xminT, xminP);
    float o1 = fmaxf(yminT, yminP);
    float o2 = fminf(xmaxT, xmaxP);
    float o3 = fminf(ymaxT, ymaxP);

    bool incorrect = (o2 < o0) || (o3 < o1);
    if (incorrect) {
        float dx = p.x - g.x;
        float dy = p.y - g.y;
        float dz = p.z - g.z;
        float dw = p.w - g.w;
        mse_acc += dx * dx + dy * dy + dz * dz + dw * dw;
        ninc++;
    } else {
        float area_p = p.z * p.w;
        float area_g = g.z * g.w;
        float inter  = (o2 - o0) * (o3 - o1);
        iou_acc += inter / (area_p + area_g - inter + 1e-7f);
    }
}

__global__ __launch_bounds__(NTHREADS, 5) void iou_fused_kernel(
    const float4* __restrict__ pr, const float4* __restrict__ gt,
    float* __restrict__ out, int n)
{
    float iou_acc = 0.0f, mse_acc = 0.0f;
    unsigned int ninc = 0u;

    const int tid    = blockIdx.x * NTHREADS + threadIdx.x;
    const int stride = NBLOCKS * NTHREADS;

    int i = tid;
    // Unroll x4: 8 independent 128-bit loads in flight per trip.
    for (; i + 3 * stride < n; i += 4 * stride) {
        float4 p0 = ldcs4(&pr[i]);
        float4 g0 = ldcs4(&gt[i]);
        float4 p1 = ldcs4(&pr[i + stride]);
        float4 g1 = ldcs4(&gt[i + stride]);
        float4 p2 = ldcs4(&pr[i + 2 * stride]);
        float4 g2 = ldcs4(&gt[i + 2 * stride]);
        float4 p3 = ldcs4(&pr[i + 3 * stride]);
        float4 g3 = ldcs4(&gt[i + 3 * stride]);
        process_box(p0, g0, iou_acc, mse_acc, ninc);
        process_box(p1, g1, iou_acc, mse_acc, ninc);
        process_box(p2, g2, iou_acc, mse_acc, ninc);
        process_box(p3, g3, iou_acc, mse_acc, ninc);
    }
    for (; i < n; i += stride) {
        process_box(ldcs4(&pr[i]), ldcs4(&gt[i]), iou_acc, mse_acc, ninc);
    }

    // ncorr is derived: boxes this thread processed minus its ninc.
    unsigned int nproc = (tid < n) ? (unsigned int)((n - tid + stride - 1) / stride) : 0u;
    unsigned int ncorr = nproc - ninc;

    // Intra-warp reduce
    #pragma unroll
    for (int off = 16; off > 0; off >>= 1) {
        iou_acc += __shfl_down_sync(0xFFFFFFFFu, iou_acc, off);
        mse_acc += __shfl_down_sync(0xFFFFFFFFu, mse_acc, off);
        ninc    += __shfl_down_sync(0xFFFFFFFFu, ninc, off);
        ncorr   += __shfl_down_sync(0xFFFFFFFFu, ncorr, off);
    }

    // Inter-warp reduce via smem
    __shared__ float s_iou[NTHREADS / 32];
    __shared__ float s_mse[NTHREADS / 32];
    __shared__ unsigned int s_ninc[NTHREADS / 32];
    const int lane = threadIdx.x & 31;
    const int warp = threadIdx.x >> 5;
    if (lane == 0) {
        s_iou[warp]  = iou_acc;
        s_mse[warp]  = mse_acc;
        s_ninc[warp] = ninc;
    }
    __syncthreads();
    if (warp == 0) {
        const int nw = NTHREADS / 32;
        float iou = (lane < nw) ? s_iou[lane] : 0.0f;
        float mse = (lane < nw) ? s_mse[lane] : 0.0f;
        unsigned int ni = (lane < nw) ? s_ninc[lane] : 0u;
        #pragma unroll
        for (int off = 4; off > 0; off >>= 1) {
            iou += __shfl_down_sync(0xFFFFFFFFu, iou, off);
            mse += __shfl_down_sync(0xFFFFFFFFu, mse, off);
            ni  += __shfl_down_sync(0xFFFFFFFFu, ni, off);
        }
        if (lane == 0) {
            g_part_iou[blockIdx.x]  = iou;
            g_part_mse[blockIdx.x]  = mse;
            g_part_ninc[blockIdx.x] = ni;
            // ncorr total = n - total ninc (derived in finalize)
        }
    }

    // Last-block-done finalization
    __shared__ bool is_last;
    if (threadIdx.x == 0) {
        __threadfence();
        unsigned int prev = atomicAdd(&g_done_count, 1u);
        is_last = (prev == (unsigned int)(gridDim.x - 1));
    }
    __syncthreads();
    if (!is_last) return;

    float iou = 0.0f, mse = 0.0f;
    unsigned long long ni = 0ull;
    for (int j = threadIdx.x; j < NBLOCKS; j += NTHREADS) {
        iou += g_part_iou[j];
        mse += g_part_mse[j];
        ni  += g_part_ninc[j];
    }
    #pragma unroll
    for (int off = 16; off > 0; off >>= 1) {
        iou += __shfl_down_sync(0xFFFFFFFFu, iou, off);
        mse += __shfl_down_sync(0xFFFFFFFFu, mse, off);
        ni  += __shfl_down_sync(0xFFFFFFFFu, ni, off);
    }
    __shared__ float f_iou[NTHREADS / 32];
    __shared__ float f_mse[NTHREADS / 32];
    __shared__ unsigned long long f_ninc[NTHREADS / 32];
    if (lane == 0) {
        f_iou[warp] = iou; f_mse[warp] = mse; f_ninc[warp] = ni;
    }
    __syncthreads();
    if (threadIdx.x == 0) {
        const int nw = NTHREADS / 32;
        double diou = 0.0, dmse = 0.0;
        unsigned long long tninc = 0ull;
        for (int w = 0; w < nw; w++) {
            diou += (double)f_iou[w];
            dmse += (double)f_mse[w];
            tninc += f_ninc[w];
        }
        unsigned long long tncorr = (unsigned long long)n - tninc;
        double mse_denom  = (double)(tninc * 4ull > 0ull ? tninc * 4ull : 1ull);
        double corr_denom = (double)(tncorr > 0ull ? tncorr : 1ull);
        float mse_mean = (float)(dmse / mse_denom);
        float iou_mean = (float)(diou / corr_denom);
        float res_full = iou_mean + (tninc > 0ull ? -mse_mean : 0.0f);
        out[0] = (tncorr > 0ull) ? res_full : -mse_mean;
        g_done_count = 0u;  // reset for next graph replay
    }
}

extern "C" void kernel_launch(void* const* d_in, const int* in_sizes, int n_in,
                              void* d_out, int out_size) {
    const float4* pr = (const float4*)d_in[0];
    const float4* gt = (const float4*)d_in[1];
    float* out = (float*)d_out;
    int n = in_sizes[0] / 4;  // floats -> boxes

    iou_fused_kernel<<<NBLOCKS, NTHREADS>>>(pr, gt, out, n);
}